// round 16
// baseline (speedup 1.0000x reference)
#include <cuda_runtime.h>
#include <cuda_bf16.h>
#include <math.h>
#include <stdint.h>

#define NNODES 50000
#define NEDGES 800000
#define DIM    128
#define NGRAPH 64
#define ETOT   (NEDGES + NNODES)
#define SCAN_B 1024
#define NSCAN  ((NNODES + SCAN_B - 1) / SCAN_B)
#define NEG_SLOPE 0.2f
#define MTILE  64
#define TILES  ((NNODES + MTILE - 1) / MTILE)     // 782
#define GEMM_GRID 296                             // 2 CTAs per SM
#define GEMM_THREADS 256

// ---------------- scratch (device globals; no allocation allowed) ----------------
__device__ float g_h [NNODES * DIM];
__device__ float g_f1[NNODES * DIM];
__device__ float g_as[NNODES];
__device__ float g_ad[NNODES];
__device__ int   g_deg   [NNODES];
__device__ int   g_rowptr[NNODES + 1];
__device__ int   g_cursor[NNODES];
__device__ int   g_csrc  [ETOT];
__device__ int   g_bsum  [NSCAN];

// ---------------- helpers ----------------
__device__ __forceinline__ float bf16f(float x) {           // float -> bf16 -> float
    return __bfloat162float(__float2bfloat16(x));
}
__device__ __forceinline__ uint32_t packbf(float k0, float k1) {  // lower=k0, upper=k1
    uint32_t r;
    asm("cvt.rn.bf16x2.f32 %0, %1, %2;" : "=r"(r) : "f"(k1), "f"(k0));
    return r;
}
__device__ __forceinline__ void mma_bf16(float* c, const uint32_t* a, uint32_t b0, uint32_t b1) {
    asm volatile("mma.sync.aligned.m16n8k16.row.col.f32.bf16.bf16.f32 "
                 "{%0,%1,%2,%3}, {%4,%5,%6,%7}, {%8,%9}, {%0,%1,%2,%3};"
                 : "+f"(c[0]), "+f"(c[1]), "+f"(c[2]), "+f"(c[3])
                 : "r"(a[0]), "r"(a[1]), "r"(a[2]), "r"(a[3]), "r"(b0), "r"(b1));
}

// smem geometry: entries are uint2 = (hi bf16x2, lo bf16x2) per k-pair.
#define PA 68
#define PB 132
struct SmemGemm {
    uint2 A[MTILE * PA];   // 64 rows x 64 k-pairs (+pad):  34,816 B
    uint2 B[64 * PB];      // 64 k-pairs x 128 cols (+pad): 67,584 B
    float asrc[128];
    float adst[128];
    float asum[MTILE];
    float adsum[MTILE];
};
#define SM_TOTAL ((int)sizeof(SmemGemm))

// ---------------- CSR build ----------------
__global__ void k_initdeg(float* __restrict__ pooled) {
    int i = blockIdx.x * blockDim.x + threadIdx.x;
    if (i < NNODES) g_deg[i] = 1;              // self-loop
    if (i < NGRAPH * DIM) pooled[i] = 0.f;     // fused pooled zeroing
}
__global__ void k_hist(const int* __restrict__ ei) {
    int e = blockIdx.x * blockDim.x + threadIdx.x;
    if (e < NEDGES) atomicAdd(&g_deg[ei[NEDGES + e]], 1);
}
__global__ void k_scan1() {
    __shared__ int sh[SCAN_B];
    int tid = threadIdx.x;
    int i = blockIdx.x * SCAN_B + tid;
    int v = (i < NNODES) ? g_deg[i] : 0;
    sh[tid] = v;
    __syncthreads();
    for (int o = 1; o < SCAN_B; o <<= 1) {
        int t = (tid >= o) ? sh[tid - o] : 0;
        __syncthreads();
        sh[tid] += t;
        __syncthreads();
    }
    if (i < NNODES) g_rowptr[i] = sh[tid] - v;
    if (tid == SCAN_B - 1) g_bsum[blockIdx.x] = sh[tid];
}
__global__ void k_scan3() {
    __shared__ int pre[NSCAN];
    int tid = threadIdx.x;
    if (tid < NSCAN) pre[tid] = g_bsum[tid];
    __syncthreads();
    if (tid == 0) {
        int acc = 0;
        for (int b = 0; b < NSCAN; b++) { int t = pre[b]; pre[b] = acc; acc += t; }
    }
    __syncthreads();
    int i = blockIdx.x * blockDim.x + tid;
    if (i < NNODES) {
        int r = g_rowptr[i] + pre[i / SCAN_B];
        g_rowptr[i] = r;
        g_cursor[i] = r;
    }
    if (i == 0) g_rowptr[NNODES] = ETOT;
}
__global__ void k_scatter(const int* __restrict__ ei) {
    int e = blockIdx.x * blockDim.x + threadIdx.x;
    if (e < NEDGES) {
        int src = ei[e];
        int dst = ei[NEDGES + e];
        g_csrc[atomicAdd(&g_cursor[dst], 1)] = src;
    } else if (e < ETOT) {
        int v = e - NEDGES;
        g_csrc[atomicAdd(&g_cursor[v], 1)] = v;
    }
}

// ---------------- 3x-bf16-split m16n8k16 GEMM + fused alpha dots ----------------
// 256 threads / 8 warps, 2 CTAs per SM. M-tile 64.
// warp w owns rows (w&3)*16.. and col half (w>>2)*64..
__global__ __launch_bounds__(GEMM_THREADS, 2) void k_gemm_mma(
        const float* __restrict__ xin, int layer,
        const float* __restrict__ W,
        const float* __restrict__ a_src,
        const float* __restrict__ a_dst) {
    extern __shared__ char smraw[];
    SmemGemm* sm = (SmemGemm*)smraw;
    const float* __restrict__ A = layer ? g_f1 : xin;

    int tid = threadIdx.x;
    int lane = tid & 31;
    int wid = tid >> 5;
    int gq = lane >> 2;
    int tq = lane & 3;
    int m0 = (wid & 3) * 16;
    int n0 = (wid >> 2) * 64;

    // W residency: B[pair p][col n] = (bf16x2(W[2p][n],W[2p+1][n]) hi, lo)
    {
        const float4* W4 = (const float4*)W;
        for (int q = tid; q < 2048; q += GEMM_THREADS) {   // 64 pairs x 32 col4-groups
            int p  = q >> 5;
            int nq = q & 31;
            float4 r0 = W4[p * 64 + nq];        // W row 2p, cols 4nq..
            float4 r1 = W4[p * 64 + 32 + nq];   // W row 2p+1
            float h0x = bf16f(r0.x), h1x = bf16f(r1.x);
            float h0y = bf16f(r0.y), h1y = bf16f(r1.y);
            float h0z = bf16f(r0.z), h1z = bf16f(r1.z);
            float h0w = bf16f(r0.w), h1w = bf16f(r1.w);
            uint2* dst = &sm->B[p * PB + nq * 4];
            uint4 q0 = make_uint4(packbf(r0.x, r1.x), packbf(r0.x - h0x, r1.x - h1x),
                                  packbf(r0.y, r1.y), packbf(r0.y - h0y, r1.y - h1y));
            uint4 q1 = make_uint4(packbf(r0.z, r1.z), packbf(r0.z - h0z, r1.z - h1z),
                                  packbf(r0.w, r1.w), packbf(r0.w - h0w, r1.w - h1w));
            *(uint4*)(dst + 0) = q0;
            *(uint4*)(dst + 2) = q1;
        }
    }
    if (tid < 128) { sm->asrc[tid] = a_src[tid]; sm->adst[tid] = a_dst[tid]; }

    // prefetch first tile (64x128 tile = 2048 float4 / 256 threads = 8 per thread)
    float4 pref[8];
    int tile0 = blockIdx.x;
    {
        int row0 = tile0 * MTILE;
#pragma unroll
        for (int i = 0; i < 8; i++) {
            int f4 = i * GEMM_THREADS + tid;
            int row = f4 >> 5;
            int c4 = (f4 & 31) * 4;
            int gr = row0 + row;
            pref[i] = (gr < NNODES) ? *(const float4*)&A[gr * 128 + c4]
                                    : make_float4(0.f, 0.f, 0.f, 0.f);
        }
    }

    for (int tile = tile0; tile < TILES; tile += GEMM_GRID) {
        int row0 = tile * MTILE;
        __syncthreads();
        // stage A: split hi/lo, pack pairs, one uint4 store per float4
#pragma unroll
        for (int i = 0; i < 8; i++) {
            int f4 = i * GEMM_THREADS + tid;
            int row = f4 >> 5;
            int pair0 = (f4 & 31) * 2;
            float4 v = pref[i];
            float hx = bf16f(v.x), hy = bf16f(v.y), hz = bf16f(v.z), hw = bf16f(v.w);
            uint4 pk = make_uint4(packbf(v.x, v.y), packbf(v.x - hx, v.y - hy),
                                  packbf(v.z, v.w), packbf(v.z - hz, v.w - hw));
            *(uint4*)&sm->A[row * PA + pair0] = pk;
        }
        __syncthreads();

        // prefetch next tile (overlaps MMA loop)
        int ntile = tile + GEMM_GRID;
        if (ntile < TILES) {
            int nrow0 = ntile * MTILE;
#pragma unroll
            for (int i = 0; i < 8; i++) {
                int f4 = i * GEMM_THREADS + tid;
                int row = f4 >> 5;
                int c4 = (f4 & 31) * 4;
                int gr = nrow0 + row;
                pref[i] = (gr < NNODES) ? *(const float4*)&A[gr * 128 + c4]
                                        : make_float4(0.f, 0.f, 0.f, 0.f);
            }
        }

        float acc[8][4];
#pragma unroll
        for (int j = 0; j < 8; j++)
#pragma unroll
            for (int q = 0; q < 4; q++) acc[j][q] = 0.f;

        const uint2* Ab = &sm->A[(m0 + gq) * PA];
#pragma unroll
        for (int ks = 0; ks < 8; ks++) {
            int kp = ks * 8;
            uint2 fa0 = Ab[kp + tq];
            uint2 fa1 = Ab[8 * PA + kp + tq];
            uint2 fa2 = Ab[kp + tq + 4];
            uint2 fa3 = Ab[8 * PA + kp + tq + 4];
            uint32_t ahi[4] = { fa0.x, fa1.x, fa2.x, fa3.x };
            uint32_t alo[4] = { fa0.y, fa1.y, fa2.y, fa3.y };
            int kb = (kp + tq) * PB + n0 + gq;
#pragma unroll
            for (int j = 0; j < 8; j++) {
                uint2 b0 = sm->B[kb + 8 * j];
                uint2 b1 = sm->B[kb + 4 * PB + 8 * j];
                mma_bf16(acc[j], ahi, b0.x, b1.x);
                mma_bf16(acc[j], ahi, b0.y, b1.y);
                mma_bf16(acc[j], alo, b0.x, b1.x);
            }
        }

        // epilogue: zero cross-warp dot accumulators, write h, reduce alpha dots
        if (tid < MTILE) { sm->asum[tid] = 0.f; sm->adsum[tid] = 0.f; }
        __syncthreads();

        int r1 = row0 + m0 + gq;
        int r2 = r1 + 8;
        float ps1 = 0.f, pd1 = 0.f, ps2 = 0.f, pd2 = 0.f;
#pragma unroll
        for (int j = 0; j < 8; j++) {
            int c0 = n0 + 8 * j + 2 * tq;
            if (r1 < NNODES) *(float2*)&g_h[r1 * 128 + c0] = make_float2(acc[j][0], acc[j][1]);
            if (r2 < NNODES) *(float2*)&g_h[r2 * 128 + c0] = make_float2(acc[j][2], acc[j][3]);
            float s0 = sm->asrc[c0], s1 = sm->asrc[c0 + 1];
            float d0 = sm->adst[c0], d1 = sm->adst[c0 + 1];
            ps1 += acc[j][0] * s0 + acc[j][1] * s1;
            pd1 += acc[j][0] * d0 + acc[j][1] * d1;
            ps2 += acc[j][2] * s0 + acc[j][3] * s1;
            pd2 += acc[j][2] * d0 + acc[j][3] * d1;
        }
#pragma unroll
        for (int o = 1; o <= 2; o <<= 1) {
            ps1 += __shfl_xor_sync(0xffffffff, ps1, o);
            pd1 += __shfl_xor_sync(0xffffffff, pd1, o);
            ps2 += __shfl_xor_sync(0xffffffff, ps2, o);
            pd2 += __shfl_xor_sync(0xffffffff, pd2, o);
        }
        if (tq == 0) {      // 2 warps (n0=0,64) accumulate per row
            atomicAdd(&sm->asum[m0 + gq], ps1);
            atomicAdd(&sm->adsum[m0 + gq], pd1);
            atomicAdd(&sm->asum[m0 + gq + 8], ps2);
            atomicAdd(&sm->adsum[m0 + gq + 8], pd2);
        }
        __syncthreads();
        if (tid < MTILE) {
            int gr = row0 + tid;
            if (gr < NNODES) { g_as[gr] = sm->asum[tid]; g_ad[gr] = sm->adsum[tid]; }
        }
    }
}

// ---------------- per-node softmax + aggregation: warp-per-node, float4 lanes ----------------
#define AGG_WARPS 8
#define WCAP 64
__global__ __launch_bounds__(256) void k_aggregate(const float* __restrict__ bias,
                                                   float* __restrict__ dout, int to_f1) {
    __shared__ float2 cache[AGG_WARPS][WCAP];   // (exp(e), src bits)

    int w = threadIdx.x >> 5;
    int lane = threadIdx.x & 31;
    int v = blockIdx.x * AGG_WARPS + w;
    if (v >= NNODES) return;

    int base = g_rowptr[v];
    int deg = g_rowptr[v + 1] - base;
    float ad = g_ad[v];
    int n1 = (deg < WCAP) ? deg : WCAP;

    float lsum = 0.f;
    for (int i = lane; i < n1; i += 32) {
        int s = g_csrc[base + i];
        float e = g_as[s] + ad;
        e = (e > 0.f) ? e : NEG_SLOPE * e;
        float ex = __expf(e);
        cache[w][i] = make_float2(ex, __int_as_float(s));
        lsum += ex;
    }
    for (int i = WCAP + lane; i < deg; i += 32) {   // rare overflow path
        int s = g_csrc[base + i];
        float e = g_as[s] + ad;
        e = (e > 0.f) ? e : NEG_SLOPE * e;
        lsum += __expf(e);
    }
#pragma unroll
    for (int o = 16; o > 0; o >>= 1) lsum += __shfl_xor_sync(0xffffffff, lsum, o);
    float scale = 1.f / (lsum + 1e-16f);
    __syncwarp();

    float4 acc = make_float4(0.f, 0.f, 0.f, 0.f);
#pragma unroll 4
    for (int j = 0; j < n1; j++) {
        float2 c = cache[w][j];
        int s = __float_as_int(c.y);
        float4 hv = *(const float4*)&g_h[s * 128 + lane * 4];
        acc.x += hv.x * c.x; acc.y += hv.y * c.x;
        acc.z += hv.z * c.x; acc.w += hv.w * c.x;
    }
    for (int j = WCAP; j < deg; j++) {              // rare overflow path
        int s = g_csrc[base + j];
        float e = g_as[s] + ad;
        e = (e > 0.f) ? e : NEG_SLOPE * e;
        float ex = __expf(e);
        float4 hv = *(const float4*)&g_h[s * 128 + lane * 4];
        acc.x += hv.x * ex; acc.y += hv.y * ex;
        acc.z += hv.z * ex; acc.w += hv.w * ex;
    }
    float4 b4 = *(const float4*)&bias[lane * 4];
    float* out = to_f1 ? g_f1 : dout;
    *(float4*)&out[v * 128 + lane * 4] = make_float4(
        b4.x + acc.x * scale, b4.y + acc.y * scale,
        b4.z + acc.z * scale, b4.w + acc.w * scale);
}

// ---------------- global mean pool ----------------
__device__ __forceinline__ int lbound(const int* a, int n, int key) {
    int lo = 0, hi = n;
    while (lo < hi) { int mid = (lo + hi) >> 1; if (a[mid] < key) lo = mid + 1; else hi = mid; }
    return lo;
}
#define POOL_CHUNKS 16
__global__ void k_pool(const float* __restrict__ feats, const int* __restrict__ batch,
                       float* __restrict__ pooled) {
    int g = blockIdx.x;
    int c = blockIdx.y;
    int tid = threadIdx.x;
    int lo = lbound(batch, NNODES, g);
    int hi = lbound(batch, NNODES, g + 1);
    int cnt = hi - lo;
    if (cnt <= 0) return;
    float acc = 0.f;
    for (int n = lo + c; n < hi; n += POOL_CHUNKS) acc += feats[n * 128 + tid];
    atomicAdd(&pooled[g * 128 + tid], acc / (float)cnt);
}

// ---------------- launch ----------------
extern "C" void kernel_launch(void* const* d_in, const int* in_sizes, int n_in,
                              void* d_out, int out_size) {
    const float* x   = (const float*)d_in[0];
    const int*   ei  = (const int*)d_in[1];
    const int*   bat = (const int*)d_in[2];
    const float* W1  = (const float*)d_in[3];
    const float* as1 = (const float*)d_in[4];
    const float* ad1 = (const float*)d_in[5];
    const float* b1  = (const float*)d_in[6];
    const float* W2  = (const float*)d_in[7];
    const float* as2 = (const float*)d_in[8];
    const float* ad2 = (const float*)d_in[9];
    const float* b2  = (const float*)d_in[10];
    float* out = (float*)d_out;
    float* pooled = out + NNODES * DIM;

    static cudaStream_t s2 = nullptr;
    static cudaEvent_t ev_fork = nullptr, ev_csr = nullptr;
    if (s2 == nullptr) {
        cudaStreamCreateWithFlags(&s2, cudaStreamNonBlocking);
        cudaEventCreateWithFlags(&ev_fork, cudaEventDisableTiming);
        cudaEventCreateWithFlags(&ev_csr, cudaEventDisableTiming);
        cudaFuncSetAttribute(k_gemm_mma, cudaFuncAttributeMaxDynamicSharedMemorySize, SM_TOTAL);
    }

    // fork: CSR build (+pooled zeroing) on s2, fully hidden under layer-1 GEMM.
    // Submission order keeps gemm1 at launch slot #4 so ncu profiles it.
    cudaEventRecord(ev_fork, 0);
    cudaStreamWaitEvent(s2, ev_fork, 0);
    k_initdeg<<<(NNODES + 255) / 256, 256, 0, s2>>>(pooled);      // #1
    k_hist<<<(NEDGES + 255) / 256, 256, 0, s2>>>(ei);             // #2
    k_scan1<<<NSCAN, SCAN_B, 0, s2>>>();                          // #3
    k_gemm_mma<<<GEMM_GRID, GEMM_THREADS, SM_TOTAL>>>(x, 0, W1, as1, ad1); // #4 <- profiled
    k_scan3<<<(NNODES + 255) / 256, 256, 0, s2>>>();              // #5
    k_scatter<<<(ETOT + 255) / 256, 256, 0, s2>>>(ei);            // #6
    cudaEventRecord(ev_csr, s2);

    int aggBlocks = (NNODES + AGG_WARPS - 1) / AGG_WARPS;

    cudaStreamWaitEvent(0, ev_csr, 0);
    k_aggregate<<<aggBlocks, 256>>>(b1, out, 1);

    k_gemm_mma<<<GEMM_GRID, GEMM_THREADS, SM_TOTAL>>>(x, 1, W2, as2, ad2);
    k_aggregate<<<aggBlocks, 256>>>(b2, out, 0);

    // pool
    dim3 pg(NGRAPH, POOL_CHUNKS);
    k_pool<<<pg, 128>>>(out, bat, pooled);
}

// round 17
// speedup vs baseline: 1.0382x; 1.0382x over previous
#include <cuda_runtime.h>
#include <cuda_bf16.h>
#include <math.h>
#include <stdint.h>

#define NNODES 50000
#define NEDGES 800000
#define DIM    128
#define NGRAPH 64
#define ETOT   (NEDGES + NNODES)
#define SCAN_B 1024
#define NSCAN  ((NNODES + SCAN_B - 1) / SCAN_B)
#define NEG_SLOPE 0.2f
#define TILES  ((NNODES + 127) / 128)
#define GEMM_GRID 148
#define GEMM_THREADS 512

// ---------------- scratch (device globals; no allocation allowed) ----------------
__device__ float g_h [NNODES * DIM];
__device__ float g_f1[NNODES * DIM];
__device__ float g_as[NNODES];
__device__ float g_ad[NNODES];
__device__ int   g_deg   [NNODES];
__device__ int   g_rowptr[NNODES + 1];
__device__ int   g_cursor[NNODES];
__device__ int   g_csrc  [ETOT];
__device__ int   g_bsum  [NSCAN];

// ---------------- helpers ----------------
__device__ __forceinline__ float bf16f(float x) {           // float -> bf16 -> float
    return __bfloat162float(__float2bfloat16(x));
}
__device__ __forceinline__ uint32_t packbf(float k0, float k1) {  // lower=k0, upper=k1
    uint32_t r;
    asm("cvt.rn.bf16x2.f32 %0, %1, %2;" : "=r"(r) : "f"(k1), "f"(k0));
    return r;
}
__device__ __forceinline__ void mma_bf16(float* c, const uint32_t* a, uint32_t b0, uint32_t b1) {
    asm volatile("mma.sync.aligned.m16n8k16.row.col.f32.bf16.bf16.f32 "
                 "{%0,%1,%2,%3}, {%4,%5,%6,%7}, {%8,%9}, {%0,%1,%2,%3};"
                 : "+f"(c[0]), "+f"(c[1]), "+f"(c[2]), "+f"(c[3])
                 : "r"(a[0]), "r"(a[1]), "r"(a[2]), "r"(a[3]), "r"(b0), "r"(b1));
}

// smem geometry: entries are uint2 = (hi bf16x2, lo bf16x2) per k-pair.
#define PA 68
#define PB 132
struct SmemGemm {
    uint2 A[128 * PA];     // 128 rows x 64 k-pairs (+pad):  69,632 B
    uint2 B[64 * PB];      // 64 k-pairs x 128 cols (+pad):  67,584 B
    float asrc[128];
    float adst[128];
    float asum[128];
    float adsum[128];
};
#define SM_TOTAL ((int)sizeof(SmemGemm))

// ---------------- CSR build ----------------
__global__ void k_initdeg(float* __restrict__ pooled) {
    int i = blockIdx.x * blockDim.x + threadIdx.x;
    if (i < NNODES) g_deg[i] = 1;              // self-loop
    if (i < NGRAPH * DIM) pooled[i] = 0.f;     // fused pooled zeroing
}
__global__ void k_hist(const int* __restrict__ ei) {
    int e = blockIdx.x * blockDim.x + threadIdx.x;
    if (e < NEDGES) atomicAdd(&g_deg[ei[NEDGES + e]], 1);
}
__global__ void k_scan1() {
    __shared__ int sh[SCAN_B];
    int tid = threadIdx.x;
    int i = blockIdx.x * SCAN_B + tid;
    int v = (i < NNODES) ? g_deg[i] : 0;
    sh[tid] = v;
    __syncthreads();
    for (int o = 1; o < SCAN_B; o <<= 1) {
        int t = (tid >= o) ? sh[tid - o] : 0;
        __syncthreads();
        sh[tid] += t;
        __syncthreads();
    }
    if (i < NNODES) g_rowptr[i] = sh[tid] - v;
    if (tid == SCAN_B - 1) g_bsum[blockIdx.x] = sh[tid];
}
__global__ void k_scan3() {
    __shared__ int pre[NSCAN];
    int tid = threadIdx.x;
    if (tid < NSCAN) pre[tid] = g_bsum[tid];
    __syncthreads();
    if (tid == 0) {
        int acc = 0;
        for (int b = 0; b < NSCAN; b++) { int t = pre[b]; pre[b] = acc; acc += t; }
    }
    __syncthreads();
    int i = blockIdx.x * blockDim.x + tid;
    if (i < NNODES) {
        int r = g_rowptr[i] + pre[i / SCAN_B];
        g_rowptr[i] = r;
        g_cursor[i] = r;
    }
    if (i == 0) g_rowptr[NNODES] = ETOT;
}
__global__ void k_scatter(const int* __restrict__ ei) {
    int e = blockIdx.x * blockDim.x + threadIdx.x;
    if (e < NEDGES) {
        int src = ei[e];
        int dst = ei[NEDGES + e];
        g_csrc[atomicAdd(&g_cursor[dst], 1)] = src;
    } else if (e < ETOT) {
        int v = e - NEDGES;
        g_csrc[atomicAdd(&g_cursor[v], 1)] = v;
    }
}

// ---------------- 3x-bf16-split m16n8k16 GEMM + fused alpha dots ----------------
// 512 threads / 16 warps: warp w owns rows (w&7)*16.. and col half (w>>3)*64..
__global__ __launch_bounds__(GEMM_THREADS, 1) void k_gemm_mma(
        const float* __restrict__ xin, int layer,
        const float* __restrict__ W,
        const float* __restrict__ a_src,
        const float* __restrict__ a_dst) {
    extern __shared__ char smraw[];
    SmemGemm* sm = (SmemGemm*)smraw;
    const float* __restrict__ A = layer ? g_f1 : xin;

    int tid = threadIdx.x;
    int lane = tid & 31;
    int wid = tid >> 5;
    int gq = lane >> 2;
    int tq = lane & 3;
    int m0 = (wid & 7) * 16;
    int n0 = (wid >> 3) * 64;

    // W residency: B[pair p][col n] = (bf16x2(W[2p][n],W[2p+1][n]) hi, lo)
    {
        const float4* W4 = (const float4*)W;
        for (int q = tid; q < 2048; q += GEMM_THREADS) {   // 64 pairs x 32 col4-groups
            int p  = q >> 5;
            int nq = q & 31;
            float4 r0 = W4[p * 64 + nq];        // W row 2p, cols 4nq..
            float4 r1 = W4[p * 64 + 32 + nq];   // W row 2p+1
            float h0x = bf16f(r0.x), h1x = bf16f(r1.x);
            float h0y = bf16f(r0.y), h1y = bf16f(r1.y);
            float h0z = bf16f(r0.z), h1z = bf16f(r1.z);
            float h0w = bf16f(r0.w), h1w = bf16f(r1.w);
            uint2* dst = &sm->B[p * PB + nq * 4];
            uint4 q0 = make_uint4(packbf(r0.x, r1.x), packbf(r0.x - h0x, r1.x - h1x),
                                  packbf(r0.y, r1.y), packbf(r0.y - h0y, r1.y - h1y));
            uint4 q1 = make_uint4(packbf(r0.z, r1.z), packbf(r0.z - h0z, r1.z - h1z),
                                  packbf(r0.w, r1.w), packbf(r0.w - h0w, r1.w - h1w));
            *(uint4*)(dst + 0) = q0;
            *(uint4*)(dst + 2) = q1;
        }
    }
    if (tid < 128) { sm->asrc[tid] = a_src[tid]; sm->adst[tid] = a_dst[tid]; }

    // prefetch first tile (8 float4 per thread = full 128x128 tile)
    float4 pref[8];
    int tile0 = blockIdx.x;
    {
        int row0 = tile0 * 128;
#pragma unroll
        for (int i = 0; i < 8; i++) {
            int f4 = i * GEMM_THREADS + tid;
            int row = f4 >> 5;
            int c4 = (f4 & 31) * 4;
            int gr = row0 + row;
            pref[i] = (gr < NNODES) ? *(const float4*)&A[gr * 128 + c4]
                                    : make_float4(0.f, 0.f, 0.f, 0.f);
        }
    }

    for (int tile = tile0; tile < TILES; tile += GEMM_GRID) {
        int row0 = tile * 128;
        __syncthreads();
        // stage A: split hi/lo, pack pairs, one uint4 store per float4
#pragma unroll
        for (int i = 0; i < 8; i++) {
            int f4 = i * GEMM_THREADS + tid;
            int row = f4 >> 5;
            int pair0 = (f4 & 31) * 2;
            float4 v = pref[i];
            float hx = bf16f(v.x), hy = bf16f(v.y), hz = bf16f(v.z), hw = bf16f(v.w);
            uint4 pk = make_uint4(packbf(v.x, v.y), packbf(v.x - hx, v.y - hy),
                                  packbf(v.z, v.w), packbf(v.z - hz, v.w - hw));
            *(uint4*)&sm->A[row * PA + pair0] = pk;
        }
        __syncthreads();

        // prefetch next tile (overlaps MMA loop)
        int ntile = tile + GEMM_GRID;
        if (ntile < TILES) {
            int nrow0 = ntile * 128;
#pragma unroll
            for (int i = 0; i < 8; i++) {
                int f4 = i * GEMM_THREADS + tid;
                int row = f4 >> 5;
                int c4 = (f4 & 31) * 4;
                int gr = nrow0 + row;
                pref[i] = (gr < NNODES) ? *(const float4*)&A[gr * 128 + c4]
                                        : make_float4(0.f, 0.f, 0.f, 0.f);
            }
        }

        float acc[8][4];
#pragma unroll
        for (int j = 0; j < 8; j++)
#pragma unroll
            for (int q = 0; q < 4; q++) acc[j][q] = 0.f;

        const uint2* Ab = &sm->A[(m0 + gq) * PA];
#pragma unroll
        for (int ks = 0; ks < 8; ks++) {
            int kp = ks * 8;
            uint2 fa0 = Ab[kp + tq];
            uint2 fa1 = Ab[8 * PA + kp + tq];
            uint2 fa2 = Ab[kp + tq + 4];
            uint2 fa3 = Ab[8 * PA + kp + tq + 4];
            uint32_t ahi[4] = { fa0.x, fa1.x, fa2.x, fa3.x };
            uint32_t alo[4] = { fa0.y, fa1.y, fa2.y, fa3.y };
            int kb = (kp + tq) * PB + n0 + gq;
#pragma unroll
            for (int j = 0; j < 8; j++) {
                uint2 b0 = sm->B[kb + 8 * j];
                uint2 b1 = sm->B[kb + 4 * PB + 8 * j];
                mma_bf16(acc[j], ahi, b0.x, b1.x);
                mma_bf16(acc[j], ahi, b0.y, b1.y);
                mma_bf16(acc[j], alo, b0.x, b1.x);
            }
        }

        // epilogue: zero cross-warp dot accumulators, write h, reduce alpha dots
        if (tid < 128) { sm->asum[tid] = 0.f; sm->adsum[tid] = 0.f; }
        __syncthreads();

        int r1 = row0 + m0 + gq;
        int r2 = r1 + 8;
        float ps1 = 0.f, pd1 = 0.f, ps2 = 0.f, pd2 = 0.f;
#pragma unroll
        for (int j = 0; j < 8; j++) {
            int c0 = n0 + 8 * j + 2 * tq;
            if (r1 < NNODES) *(float2*)&g_h[r1 * 128 + c0] = make_float2(acc[j][0], acc[j][1]);
            if (r2 < NNODES) *(float2*)&g_h[r2 * 128 + c0] = make_float2(acc[j][2], acc[j][3]);
            float s0 = sm->asrc[c0], s1 = sm->asrc[c0 + 1];
            float d0 = sm->adst[c0], d1 = sm->adst[c0 + 1];
            ps1 += acc[j][0] * s0 + acc[j][1] * s1;
            pd1 += acc[j][0] * d0 + acc[j][1] * d1;
            ps2 += acc[j][2] * s0 + acc[j][3] * s1;
            pd2 += acc[j][2] * d0 + acc[j][3] * d1;
        }
#pragma unroll
        for (int o = 1; o <= 2; o <<= 1) {
            ps1 += __shfl_xor_sync(0xffffffff, ps1, o);
            pd1 += __shfl_xor_sync(0xffffffff, pd1, o);
            ps2 += __shfl_xor_sync(0xffffffff, ps2, o);
            pd2 += __shfl_xor_sync(0xffffffff, pd2, o);
        }
        if (tq == 0) {      // 2 warps (n0=0,64) accumulate per row
            atomicAdd(&sm->asum[m0 + gq], ps1);
            atomicAdd(&sm->adsum[m0 + gq], pd1);
            atomicAdd(&sm->asum[m0 + gq + 8], ps2);
            atomicAdd(&sm->adsum[m0 + gq + 8], pd2);
        }
        __syncthreads();
        if (tid < 128) {
            int gr = row0 + tid;
            if (gr < NNODES) { g_as[gr] = sm->asum[tid]; g_ad[gr] = sm->adsum[tid]; }
        }
    }
}

// ---------------- per-node softmax + aggregation: warp-per-node, float4 lanes ----------------
#define AGG_WARPS 8
#define WCAP 64
__global__ __launch_bounds__(256) void k_aggregate(const float* __restrict__ bias,
                                                   float* __restrict__ dout, int to_f1) {
    __shared__ float2 cache[AGG_WARPS][WCAP];   // (exp(e), src bits)

    int w = threadIdx.x >> 5;
    int lane = threadIdx.x & 31;
    int v = blockIdx.x * AGG_WARPS + w;
    if (v >= NNODES) return;

    int base = g_rowptr[v];
    int deg = g_rowptr[v + 1] - base;
    float ad = g_ad[v];
    int n1 = (deg < WCAP) ? deg : WCAP;

    float lsum = 0.f;
    for (int i = lane; i < n1; i += 32) {
        int s = g_csrc[base + i];
        float e = g_as[s] + ad;
        e = (e > 0.f) ? e : NEG_SLOPE * e;
        float ex = __expf(e);
        cache[w][i] = make_float2(ex, __int_as_float(s));
        lsum += ex;
    }
    for (int i = WCAP + lane; i < deg; i += 32) {   // rare overflow path
        int s = g_csrc[base + i];
        float e = g_as[s] + ad;
        e = (e > 0.f) ? e : NEG_SLOPE * e;
        lsum += __expf(e);
    }
#pragma unroll
    for (int o = 16; o > 0; o >>= 1) lsum += __shfl_xor_sync(0xffffffff, lsum, o);
    float scale = 1.f / (lsum + 1e-16f);
    __syncwarp();

    float4 acc = make_float4(0.f, 0.f, 0.f, 0.f);
#pragma unroll 4
    for (int j = 0; j < n1; j++) {
        float2 c = cache[w][j];
        int s = __float_as_int(c.y);
        float4 hv = *(const float4*)&g_h[s * 128 + lane * 4];
        acc.x += hv.x * c.x; acc.y += hv.y * c.x;
        acc.z += hv.z * c.x; acc.w += hv.w * c.x;
    }
    for (int j = WCAP; j < deg; j++) {              // rare overflow path
        int s = g_csrc[base + j];
        float e = g_as[s] + ad;
        e = (e > 0.f) ? e : NEG_SLOPE * e;
        float ex = __expf(e);
        float4 hv = *(const float4*)&g_h[s * 128 + lane * 4];
        acc.x += hv.x * ex; acc.y += hv.y * ex;
        acc.z += hv.z * ex; acc.w += hv.w * ex;
    }
    float4 b4 = *(const float4*)&bias[lane * 4];
    float* out = to_f1 ? g_f1 : dout;
    *(float4*)&out[v * 128 + lane * 4] = make_float4(
        b4.x + acc.x * scale, b4.y + acc.y * scale,
        b4.z + acc.z * scale, b4.w + acc.w * scale);
}

// ---------------- global mean pool ----------------
__device__ __forceinline__ int lbound(const int* a, int n, int key) {
    int lo = 0, hi = n;
    while (lo < hi) { int mid = (lo + hi) >> 1; if (a[mid] < key) lo = mid + 1; else hi = mid; }
    return lo;
}
#define POOL_CHUNKS 32
__global__ void k_pool(const float* __restrict__ feats, const int* __restrict__ batch,
                       float* __restrict__ pooled) {
    int g = blockIdx.x;
    int c = blockIdx.y;
    int tid = threadIdx.x;
    int lo = lbound(batch, NNODES, g);
    int hi = lbound(batch, NNODES, g + 1);
    int cnt = hi - lo;
    if (cnt <= 0) return;
    float acc = 0.f;
    for (int n = lo + c; n < hi; n += POOL_CHUNKS) acc += feats[n * 128 + tid];
    atomicAdd(&pooled[g * 128 + tid], acc / (float)cnt);
}

// ---------------- launch ----------------
extern "C" void kernel_launch(void* const* d_in, const int* in_sizes, int n_in,
                              void* d_out, int out_size) {
    const float* x   = (const float*)d_in[0];
    const int*   ei  = (const int*)d_in[1];
    const int*   bat = (const int*)d_in[2];
    const float* W1  = (const float*)d_in[3];
    const float* as1 = (const float*)d_in[4];
    const float* ad1 = (const float*)d_in[5];
    const float* b1  = (const float*)d_in[6];
    const float* W2  = (const float*)d_in[7];
    const float* as2 = (const float*)d_in[8];
    const float* ad2 = (const float*)d_in[9];
    const float* b2  = (const float*)d_in[10];
    float* out = (float*)d_out;
    float* pooled = out + NNODES * DIM;

    static cudaStream_t s2 = nullptr;
    static cudaEvent_t ev_fork = nullptr, ev_csr = nullptr;
    if (s2 == nullptr) {
        cudaStreamCreateWithFlags(&s2, cudaStreamNonBlocking);
        cudaEventCreateWithFlags(&ev_fork, cudaEventDisableTiming);
        cudaEventCreateWithFlags(&ev_csr, cudaEventDisableTiming);
        cudaFuncSetAttribute(k_gemm_mma, cudaFuncAttributeMaxDynamicSharedMemorySize, SM_TOTAL);
    }

    // fork: CSR build (+pooled zeroing) on s2, fully hidden under layer-1 GEMM.
    // Submission order keeps gemm1 at launch slot #4 so ncu profiles it.
    cudaEventRecord(ev_fork, 0);
    cudaStreamWaitEvent(s2, ev_fork, 0);
    k_initdeg<<<(NNODES + 255) / 256, 256, 0, s2>>>(pooled);      // #1
    k_hist<<<(NEDGES + 255) / 256, 256, 0, s2>>>(ei);             // #2
    k_scan1<<<NSCAN, SCAN_B, 0, s2>>>();                          // #3
    k_gemm_mma<<<GEMM_GRID, GEMM_THREADS, SM_TOTAL>>>(x, 0, W1, as1, ad1); // #4 <- profiled
    k_scan3<<<(NNODES + 255) / 256, 256, 0, s2>>>();              // #5
    k_scatter<<<(ETOT + 255) / 256, 256, 0, s2>>>(ei);            // #6
    cudaEventRecord(ev_csr, s2);

    int aggBlocks = (NNODES + AGG_WARPS - 1) / AGG_WARPS;

    cudaStreamWaitEvent(0, ev_csr, 0);
    k_aggregate<<<aggBlocks, 256>>>(b1, out, 1);

    k_gemm_mma<<<GEMM_GRID, GEMM_THREADS, SM_TOTAL>>>(x, 1, W2, as2, ad2);
    k_aggregate<<<aggBlocks, 256>>>(b2, out, 0);

    // pool
    dim3 pg(NGRAPH, POOL_CHUNKS);
    k_pool<<<pg, 128>>>(out, bat, pooled);
}